// round 8
// baseline (speedup 1.0000x reference)
#include <cuda_runtime.h>
#include <math.h>

#define NVEC   350      // float4 per disease row (1400/4)
#define EPSF   1e-6f
#define MAXN   4096     // survival rows
#define IGRP   4        // i's per concordance block (1024 blocks -> high occ)

// slotted accumulators: 128B stride -> each slot on its own L2 line
#define NSLOT  32
#define SSTRIDE 32
#define M_DIS  0
#define M_DCNT 1
#define M_TIME 2
#define M_RISK 3
#define M_RCNT 4
#define M_UNC  5
#define M_CONC 6
#define M_PAIR 7
#define NMET   8

// zero at module load; the finalizing block resets after reading, so every
// execution (correctness run + each graph replay) starts from zeros.
__device__ float        g_acc[NMET][NSLOT * SSTRIDE];
__device__ float2       g_tm[MAXN];        // packed (time_target, row_mean)
__device__ unsigned int g_done;

__device__ __forceinline__ void slot_add(int metric, int slot, float v) {
    atomicAdd(&g_acc[metric][slot * SSTRIDE], v);
}

__device__ __forceinline__ float warp_sum(float v) {
    #pragma unroll
    for (int o = 16; o > 0; o >>= 1) v += __shfl_xor_sync(0xffffffff, v, o);
    return v;
}
__device__ __forceinline__ float warp_max(float v) {
    #pragma unroll
    for (int o = 16; o > 0; o >>= 1) v = fmaxf(v, __shfl_xor_sync(0xffffffff, v, o));
    return v;
}

// ---------------- kernel 1: disease CE + row means + small per-token losses --
__global__ void __launch_bounds__(128) disease_ce_kernel(
        const float* __restrict__ logits, const int* __restrict__ targets,
        const float* __restrict__ tte, const float* __restrict__ ttgt,
        const float* __restrict__ risk, const int* __restrict__ rtgt,
        const float* __restrict__ unc,
        const float* __restrict__ curves, const float* __restrict__ ttimes,
        int n_surv, int T) {
    int row  = blockIdx.x;
    int t    = threadIdx.x;
    int slot = row & (NSLOT - 1);
    const float4* base = reinterpret_cast<const float4*>(logits) + (size_t)row * NVEC;

    float4 v0 = base[t];                  // t in [0,128) < 350
    float4 v1 = base[t + 128];            // < 350
    bool   h2 = (t + 256) < NVEC;         // t < 94
    float4 v2 = h2 ? base[t + 256]
                   : make_float4(-INFINITY, -INFINITY, -INFINITY, -INFINITY);

    // ---- fused survival row mean: warp 1 handles row < n_surv ----
    if (row < n_surv && t >= 32 && t < 64) {
        int lane = t - 32;
        const float* crow = curves + (size_t)row * T;
        float s = 0.f;
        for (int k = lane; k < T; k += 32) s += crow[k];
        #pragma unroll
        for (int o = 16; o > 0; o >>= 1) s += __shfl_xor_sync(0xffffffff, s, o, 32);
        if (lane == 0) g_tm[row] = make_float2(ttimes[row], s / (float)T);
    }

    // ---- fused per-token scalar losses (idle-lane work) ----
    if (t == 96) {
        float x    = tte[row];
        float rate = 1.0f / (x + EPSF);
        float tl   = __logf(rate + EPSF) - rate * ttgt[row];
        slot_add(M_TIME, slot, tl);
        slot_add(M_UNC,  slot, unc[row]);
    } else if (t == 64) {
        int r = rtgt[row];
        if (r >= 0) {
            const float* rl = risk + (size_t)row * 5;
            float a0 = rl[0], a1 = rl[1], a2 = rl[2], a3 = rl[3], a4 = rl[4];
            float mm = fmaxf(fmaxf(fmaxf(a0, a1), fmaxf(a2, a3)), a4);
            float ss = __expf(a0 - mm) + __expf(a1 - mm) + __expf(a2 - mm)
                     + __expf(a3 - mm) + __expf(a4 - mm);
            float xt = (r == 0) ? a0 : (r == 1) ? a1 : (r == 2) ? a2 : (r == 3) ? a3 : a4;
            slot_add(M_RISK, slot, -(xt - mm - __logf(ss)));
            slot_add(M_RCNT, slot, 1.0f);
        }
    }

    float m = fmaxf(fmaxf(fmaxf(v0.x, v0.y), fmaxf(v0.z, v0.w)),
                    fmaxf(fmaxf(v1.x, v1.y), fmaxf(v1.z, v1.w)));
    m = fmaxf(m, fmaxf(fmaxf(v2.x, v2.y), fmaxf(v2.z, v2.w)));

    __shared__ float sred[4];
    __shared__ float s_tval;

    int tgt = targets[row];
    if (tgt >= 0) {
        int vi = tgt >> 2;
        if ((vi & 127) == t) {
            float4 v = (vi < 128) ? v0 : ((vi < 256) ? v1 : v2);
            int l = tgt & 3;
            s_tval = (l == 0) ? v.x : (l == 1) ? v.y : (l == 2) ? v.z : v.w;
        }
    }

    m = warp_max(m);
    int warp = t >> 5;
    if ((t & 31) == 0) sred[warp] = m;
    __syncthreads();
    m = fmaxf(fmaxf(sred[0], sred[1]), fmaxf(sred[2], sred[3]));

    float s = __expf(v0.x - m) + __expf(v0.y - m) + __expf(v0.z - m) + __expf(v0.w - m)
            + __expf(v1.x - m) + __expf(v1.y - m) + __expf(v1.z - m) + __expf(v1.w - m);
    if (h2)
        s += __expf(v2.x - m) + __expf(v2.y - m) + __expf(v2.z - m) + __expf(v2.w - m);

    s = warp_sum(s);
    __syncthreads();
    if ((t & 31) == 0) sred[warp] = s;
    __syncthreads();

    if (t == 0 && tgt >= 0) {
        float S   = sred[0] + sred[1] + sred[2] + sred[3];
        float nll = -(s_tval - m - __logf(S));
        slot_add(M_DIS,  slot, nll);
        slot_add(M_DCNT, slot, 1.0f);
    }
}

// ------- kernel 2: concordance via warp-ballot popcount + fused finalize ----
__global__ void __launch_bounds__(128) concordance_kernel(
        const int* __restrict__ events, int n,
        float* __restrict__ out, int n_tok) {
    int tid  = threadIdx.x;
    int lane = tid & 31;
    int wrp  = tid >> 5;                   // 0..3
    int i0   = blockIdx.x * IGRP;

    __shared__ int sev[IGRP];
    if (tid < IGRP) sev[tid] = (i0 + tid < n) ? events[i0 + tid] : 0;
    __syncthreads();

    float ti[IGRP], mi[IGRP];
    bool  ev[IGRP];
    bool  any = false;
    #pragma unroll
    for (int k = 0; k < IGRP; k++) {
        float2 v = g_tm[i0 + k];           // L2 broadcast
        ti[k] = v.x; mi[k] = v.y;
        ev[k] = (sev[k] == 1);
        any |= ev[k];
    }

    unsigned cnt_i = 0, conc2_i = 0;       // conc scaled by 2 (0.5 -> 1)

    if (any) {
        // peel j in (i0, i0+IGRP): only thread 0 (<= 6 scalar pair checks)
        if (tid == 0) {
            for (int j = i0 + 1; j < i0 + IGRP && j < n; j++) {
                float2 jm = g_tm[j];
                for (int k = 0; k < j - i0; k++) {
                    if (ev[k] && ti[k] < jm.x) {
                        cnt_i++;
                        conc2_i += (mi[k] < jm.y) ? 2u : ((mi[k] == jm.y) ? 1u : 0u);
                    }
                }
            }
        }

        // main sweep: warp-cooperative, ballot+popc covers 32 pairs per k
        for (int jb = i0 + IGRP + wrp * 32; jb < n; jb += 128) {
            int j = jb + lane;
            float tj, mj;
            if (j < n) {
                float2 jm = __ldg(&g_tm[j]);
                tj = jm.x; mj = jm.y;
            } else {
                tj = -INFINITY; mj = 0.f;  // ti < -inf never true -> excluded
            }
            #pragma unroll
            for (int k = 0; k < IGRP; k++) {
                if (!ev[k]) continue;      // warp-uniform branch
                bool c1 = (ti[k] < tj);
                unsigned b1 = __ballot_sync(0xffffffff, c1);
                unsigned b2 = __ballot_sync(0xffffffff, c1 && (mi[k] <  mj));
                unsigned b3 = __ballot_sync(0xffffffff, c1 && (mi[k] <= mj));
                cnt_i   += __popc(b1);
                conc2_i += __popc(b2) + __popc(b3);   // 2*[m<] + [m==]
            }
        }
    }

    // cnt_i/conc2_i are warp-uniform (plus tid0's peel extras); reduce lane0s
    __shared__ unsigned sc_[4], si_[4];
    if (lane == 0) { sc_[wrp] = conc2_i; si_[wrp] = cnt_i; }
    __syncthreads();
    if (tid == 0) {
        unsigned C2 = sc_[0] + sc_[1] + sc_[2] + sc_[3];
        unsigned P  = si_[0] + si_[1] + si_[2] + si_[3];
        if (P > 0) {
            int slot = blockIdx.x & (NSLOT - 1);
            slot_add(M_CONC, slot, 0.5f * (float)C2);
            slot_add(M_PAIR, slot, (float)P);
        }
    }

    // ---- last-done block finalizes and resets ----
    __shared__ bool amLast;
    if (tid == 0) {
        __threadfence();
        unsigned v = atomicAdd(&g_done, 1u);
        amLast = (v == gridDim.x - 1);
    }
    __syncthreads();
    if (!amLast) return;

    __shared__ float tot[NMET];
    if (tid < NMET) {
        float s = 0.f;
        #pragma unroll
        for (int k = 0; k < NSLOT; k++) s += g_acc[tid][k * SSTRIDE];
        tot[tid] = s;
    }
    __syncthreads();
    if (tid == 0) {
        float dcnt    = tot[M_DCNT] > 0.f ? tot[M_DCNT] : 1.f;
        float rcnt    = tot[M_RCNT] > 0.f ? tot[M_RCNT] : 1.f;
        float disease = tot[M_DIS] / dcnt;
        float timel   = -tot[M_TIME] / (float)n_tok;
        float riskl   = tot[M_RISK] / rcnt;
        float surv    = (tot[M_PAIR] > 0.f) ? 1.0f - tot[M_CONC] / tot[M_PAIR] : 0.0f;
        float u       = (tot[M_UNC] / (float)n_tok) * 0.01f;
        out[0] = disease;
        out[1] = timel;
        out[2] = riskl;
        out[3] = surv;
        out[4] = u;
        out[5] = disease + timel + riskl + surv + u;
        g_done = 0u;
    }
    // reset accumulators for the next execution (128 threads, 256 entries)
    for (int e = tid; e < NMET * NSLOT; e += 128)
        g_acc[e / NSLOT][(e % NSLOT) * SSTRIDE] = 0.f;
}

// ---------------- launch ----------------
extern "C" void kernel_launch(void* const* d_in, const int* in_sizes, int n_in,
                              void* d_out, int out_size) {
    const float* disease_logits = (const float*)d_in[0];
    const int*   disease_tgt    = (const int*)d_in[1];
    const float* tte            = (const float*)d_in[2];
    const float* ttgt           = (const float*)d_in[3];
    const float* risk           = (const float*)d_in[4];
    const int*   risk_tgt       = (const int*)d_in[5];
    const float* curves         = (const float*)d_in[6];
    const float* surv_tgt       = (const float*)d_in[7];
    const int*   events         = (const int*)d_in[8];
    const float* unc            = (const float*)d_in[9];
    float*       out            = (float*)d_out;

    int n_tok = in_sizes[1];            // 16384
    int n     = in_sizes[7];            // 4096
    int T     = in_sizes[6] / n;        // 120

    disease_ce_kernel<<<n_tok, 128>>>(disease_logits, disease_tgt,
                                      tte, ttgt, risk, risk_tgt, unc,
                                      curves, surv_tgt, n, T);
    int conc_blocks = (n + IGRP - 1) / IGRP;   // 1024
    concordance_kernel<<<conc_blocks, 128>>>(events, n, out, n_tok);
}

// round 9
// speedup vs baseline: 1.1789x; 1.1789x over previous
#include <cuda_runtime.h>
#include <math.h>

#define NVEC   350      // float4 per disease row (1400/4)
#define EPSF   1e-6f
#define MAXN   4096     // survival rows
#define IGRP   4        // i's per group

// slotted accumulators: 128B stride -> each slot on its own L2 line
#define NSLOT  32
#define SSTRIDE 32
#define M_DIS  0
#define M_DCNT 1
#define M_TIME 2
#define M_RISK 3
#define M_RCNT 4
#define M_UNC  5
#define M_CONC 6
#define M_PAIR 7
#define NMET   8

// zero at module load; the finalizing block resets after reading, so every
// execution (correctness run + each graph replay) starts from zeros.
__device__ float        g_acc[NMET][NSLOT * SSTRIDE];
__device__ float2       g_tm[MAXN];        // packed (time_target, row_mean)
__device__ unsigned int g_done;

__device__ __forceinline__ void slot_add(int metric, int slot, float v) {
    atomicAdd(&g_acc[metric][slot * SSTRIDE], v);
}

__device__ __forceinline__ float warp_sum(float v) {
    #pragma unroll
    for (int o = 16; o > 0; o >>= 1) v += __shfl_xor_sync(0xffffffff, v, o);
    return v;
}
__device__ __forceinline__ unsigned warp_sum_u(unsigned v) {
    #pragma unroll
    for (int o = 16; o > 0; o >>= 1) v += __shfl_xor_sync(0xffffffff, v, o);
    return v;
}
__device__ __forceinline__ float warp_max(float v) {
    #pragma unroll
    for (int o = 16; o > 0; o >>= 1) v = fmaxf(v, __shfl_xor_sync(0xffffffff, v, o));
    return v;
}

// ---------------- kernel 1: disease CE + row means + small per-token losses --
__global__ void __launch_bounds__(128) disease_ce_kernel(
        const float* __restrict__ logits, const int* __restrict__ targets,
        const float* __restrict__ tte, const float* __restrict__ ttgt,
        const float* __restrict__ risk, const int* __restrict__ rtgt,
        const float* __restrict__ unc,
        const float* __restrict__ curves, const float* __restrict__ ttimes,
        int n_surv, int T) {
    int row  = blockIdx.x;
    int t    = threadIdx.x;
    int slot = row & (NSLOT - 1);
    const float4* base = reinterpret_cast<const float4*>(logits) + (size_t)row * NVEC;

    float4 v0 = base[t];                  // t in [0,128) < 350
    float4 v1 = base[t + 128];            // < 350
    bool   h2 = (t + 256) < NVEC;         // t < 94
    float4 v2 = h2 ? base[t + 256]
                   : make_float4(-INFINITY, -INFINITY, -INFINITY, -INFINITY);

    // ---- fused survival row mean: warp 1 handles row < n_surv ----
    if (row < n_surv && t >= 32 && t < 64) {
        int lane = t - 32;
        const float* crow = curves + (size_t)row * T;
        float s = 0.f;
        for (int k = lane; k < T; k += 32) s += crow[k];
        #pragma unroll
        for (int o = 16; o > 0; o >>= 1) s += __shfl_xor_sync(0xffffffff, s, o, 32);
        if (lane == 0) g_tm[row] = make_float2(ttimes[row], s / (float)T);
    }

    // ---- fused per-token scalar losses (idle-lane work) ----
    if (t == 96) {
        float x    = tte[row];
        float rate = 1.0f / (x + EPSF);
        float tl   = __logf(rate + EPSF) - rate * ttgt[row];
        slot_add(M_TIME, slot, tl);
        slot_add(M_UNC,  slot, unc[row]);
    } else if (t == 64) {
        int r = rtgt[row];
        if (r >= 0) {
            const float* rl = risk + (size_t)row * 5;
            float a0 = rl[0], a1 = rl[1], a2 = rl[2], a3 = rl[3], a4 = rl[4];
            float mm = fmaxf(fmaxf(fmaxf(a0, a1), fmaxf(a2, a3)), a4);
            float ss = __expf(a0 - mm) + __expf(a1 - mm) + __expf(a2 - mm)
                     + __expf(a3 - mm) + __expf(a4 - mm);
            float xt = (r == 0) ? a0 : (r == 1) ? a1 : (r == 2) ? a2 : (r == 3) ? a3 : a4;
            slot_add(M_RISK, slot, -(xt - mm - __logf(ss)));
            slot_add(M_RCNT, slot, 1.0f);
        }
    }

    float m = fmaxf(fmaxf(fmaxf(v0.x, v0.y), fmaxf(v0.z, v0.w)),
                    fmaxf(fmaxf(v1.x, v1.y), fmaxf(v1.z, v1.w)));
    m = fmaxf(m, fmaxf(fmaxf(v2.x, v2.y), fmaxf(v2.z, v2.w)));

    __shared__ float sred[4];
    __shared__ float s_tval;

    int tgt = targets[row];
    if (tgt >= 0) {
        int vi = tgt >> 2;
        if ((vi & 127) == t) {
            float4 v = (vi < 128) ? v0 : ((vi < 256) ? v1 : v2);
            int l = tgt & 3;
            s_tval = (l == 0) ? v.x : (l == 1) ? v.y : (l == 2) ? v.z : v.w;
        }
    }

    m = warp_max(m);
    int warp = t >> 5;
    if ((t & 31) == 0) sred[warp] = m;
    __syncthreads();
    m = fmaxf(fmaxf(sred[0], sred[1]), fmaxf(sred[2], sred[3]));

    float s = __expf(v0.x - m) + __expf(v0.y - m) + __expf(v0.z - m) + __expf(v0.w - m)
            + __expf(v1.x - m) + __expf(v1.y - m) + __expf(v1.z - m) + __expf(v1.w - m);
    if (h2)
        s += __expf(v2.x - m) + __expf(v2.y - m) + __expf(v2.z - m) + __expf(v2.w - m);

    s = warp_sum(s);
    __syncthreads();
    if ((t & 31) == 0) sred[warp] = s;
    __syncthreads();

    if (t == 0 && tgt >= 0) {
        float S   = sred[0] + sred[1] + sred[2] + sred[3];
        float nll = -(s_tval - m - __logf(S));
        slot_add(M_DIS,  slot, nll);
        slot_add(M_DCNT, slot, 1.0f);
    }
}

// ------- kernel 2: concordance — balanced triangle, MLP-4, predicated int ---
// process one i-group [i0, i0+IGRP): accumulate into cnt / conc2 (per lane)
__device__ __forceinline__ void conc_group(
        int i0, int n, const int* __restrict__ events,
        int tid, int lane, int wrp,
        unsigned& cnt, unsigned& conc2) {
    float ti[IGRP], mi[IGRP];
    bool  ev[IGRP];
    bool  any = false;
    #pragma unroll
    for (int k = 0; k < IGRP; k++) {
        float2 v = __ldg(&g_tm[i0 + k]);   // L2 broadcast
        ti[k] = v.x; mi[k] = v.y;
        ev[k] = (i0 + k < n) && (__ldg(&events[i0 + k]) == 1);
        any |= ev[k];
    }
    if (!any) return;

    // peel j in (i0, i0+IGRP): thread 0 only (<= 6 scalar pair checks)
    if (tid == 0) {
        for (int j = i0 + 1; j < i0 + IGRP && j < n; j++) {
            float2 jm = __ldg(&g_tm[j]);
            for (int k = 0; k < j - i0; k++) {
                if (ev[k] && ti[k] < jm.x) {
                    cnt++;
                    conc2 += (mi[k] < jm.y) ? 2u : ((mi[k] == jm.y) ? 1u : 0u);
                }
            }
        }
    }

    // main sweep: 4 warps x 4-tile unroll (128 j per warp-iter, MLP=4)
    int jstart = i0 + IGRP;
    for (int jb = jstart + wrp * 128; jb < n; jb += 512) {
        float tj[4], mj[4];
        #pragma unroll
        for (int u = 0; u < 4; u++) {
            int j = jb + u * 32 + lane;
            if (j < n) {
                float2 v = __ldg(&g_tm[j]);
                tj[u] = v.x; mj[u] = v.y;
            } else {
                tj[u] = -INFINITY; mj[u] = 0.f;   // ti < -inf never true
            }
        }
        #pragma unroll
        for (int u = 0; u < 4; u++) {
            #pragma unroll
            for (int k = 0; k < IGRP; k++) {
                if (!ev[k]) continue;              // warp-uniform branch
                bool c1 = (ti[k] < tj[u]);
                cnt   += c1;
                conc2 += (unsigned)(c1 & (mi[k] <  mj[u]))
                       + (unsigned)(c1 & (mi[k] <= mj[u]));
            }
        }
    }
}

__global__ void __launch_bounds__(128) concordance_kernel(
        const int* __restrict__ events, int n, int ngrp,
        float* __restrict__ out, int n_tok) {
    int tid  = threadIdx.x;
    int lane = tid & 31;
    int wrp  = tid >> 5;                   // 0..3

    unsigned cnt = 0, conc2 = 0;           // per-lane; conc scaled by 2

    // balanced triangle: block b owns groups b and ngrp-1-b
    int g1 = blockIdx.x;
    int g2 = ngrp - 1 - g1;
    conc_group(g1 * IGRP, n, events, tid, lane, wrp, cnt, conc2);
    if (g2 != g1)
        conc_group(g2 * IGRP, n, events, tid, lane, wrp, cnt, conc2);

    cnt   = warp_sum_u(cnt);
    conc2 = warp_sum_u(conc2);
    __shared__ unsigned sc_[4], si_[4];
    if (lane == 0) { sc_[wrp] = conc2; si_[wrp] = cnt; }
    __syncthreads();
    if (tid == 0) {
        unsigned C2 = sc_[0] + sc_[1] + sc_[2] + sc_[3];
        unsigned P  = si_[0] + si_[1] + si_[2] + si_[3];
        if (P > 0) {
            int slot = blockIdx.x & (NSLOT - 1);
            slot_add(M_CONC, slot, 0.5f * (float)C2);
            slot_add(M_PAIR, slot, (float)P);
        }
    }

    // ---- last-done block finalizes and resets (512 blocks: cheap) ----
    __shared__ bool amLast;
    if (tid == 0) {
        __threadfence();
        unsigned v = atomicAdd(&g_done, 1u);
        amLast = (v == gridDim.x - 1);
    }
    __syncthreads();
    if (!amLast) return;

    __shared__ float tot[NMET];
    if (tid < NMET) {
        float s = 0.f;
        #pragma unroll
        for (int k = 0; k < NSLOT; k++) s += g_acc[tid][k * SSTRIDE];
        tot[tid] = s;
    }
    __syncthreads();
    if (tid == 0) {
        float dcnt    = tot[M_DCNT] > 0.f ? tot[M_DCNT] : 1.f;
        float rcnt    = tot[M_RCNT] > 0.f ? tot[M_RCNT] : 1.f;
        float disease = tot[M_DIS] / dcnt;
        float timel   = -tot[M_TIME] / (float)n_tok;
        float riskl   = tot[M_RISK] / rcnt;
        float surv    = (tot[M_PAIR] > 0.f) ? 1.0f - tot[M_CONC] / tot[M_PAIR] : 0.0f;
        float u       = (tot[M_UNC] / (float)n_tok) * 0.01f;
        out[0] = disease;
        out[1] = timel;
        out[2] = riskl;
        out[3] = surv;
        out[4] = u;
        out[5] = disease + timel + riskl + surv + u;
        g_done = 0u;
    }
    // reset accumulators for the next execution (128 threads, 256 entries)
    for (int e = tid; e < NMET * NSLOT; e += 128)
        g_acc[e / NSLOT][(e % NSLOT) * SSTRIDE] = 0.f;
}

// ---------------- launch ----------------
extern "C" void kernel_launch(void* const* d_in, const int* in_sizes, int n_in,
                              void* d_out, int out_size) {
    const float* disease_logits = (const float*)d_in[0];
    const int*   disease_tgt    = (const int*)d_in[1];
    const float* tte            = (const float*)d_in[2];
    const float* ttgt           = (const float*)d_in[3];
    const float* risk           = (const float*)d_in[4];
    const int*   risk_tgt       = (const int*)d_in[5];
    const float* curves         = (const float*)d_in[6];
    const float* surv_tgt       = (const float*)d_in[7];
    const int*   events         = (const int*)d_in[8];
    const float* unc            = (const float*)d_in[9];
    float*       out            = (float*)d_out;

    int n_tok = in_sizes[1];            // 16384
    int n     = in_sizes[7];            // 4096
    int T     = in_sizes[6] / n;        // 120

    disease_ce_kernel<<<n_tok, 128>>>(disease_logits, disease_tgt,
                                      tte, ttgt, risk, risk_tgt, unc,
                                      curves, surv_tgt, n, T);
    int ngrp        = (n + IGRP - 1) / IGRP;       // 1024
    int conc_blocks = (ngrp + 1) / 2;              // 512 balanced blocks
    concordance_kernel<<<conc_blocks, 128>>>(events, n, ngrp, out, n_tok);
}

// round 10
// speedup vs baseline: 1.2487x; 1.0592x over previous
#include <cuda_runtime.h>
#include <math.h>

#define NVEC   350      // float4 per disease row (1400/4)
#define EPSF   1e-6f
#define MAXN   4096     // survival rows
#define IGRP   4        // i's per group

// slotted accumulators: 128B stride -> each slot on its own L2 line
#define NSLOT  32
#define SSTRIDE 32
#define M_DIS  0
#define M_DCNT 1
#define M_TIME 2
#define M_RISK 3
#define M_RCNT 4
#define M_UNC  5
#define M_CONC 6
#define M_PAIR 7
#define NMET   8

// zero at module load; the finalizing block resets after reading, so every
// execution (correctness run + each graph replay) starts from zeros.
__device__ float        g_acc[NMET][NSLOT * SSTRIDE];
__device__ float2       g_tm[MAXN];        // packed (time_target, row_mean)
__device__ unsigned int g_done;

__device__ __forceinline__ void slot_add(int metric, int slot, float v) {
    atomicAdd(&g_acc[metric][slot * SSTRIDE], v);
}

__device__ __forceinline__ float warp_sum(float v) {
    #pragma unroll
    for (int o = 16; o > 0; o >>= 1) v += __shfl_xor_sync(0xffffffff, v, o);
    return v;
}
__device__ __forceinline__ unsigned warp_sum_u(unsigned v) {
    #pragma unroll
    for (int o = 16; o > 0; o >>= 1) v += __shfl_xor_sync(0xffffffff, v, o);
    return v;
}
__device__ __forceinline__ float warp_max(float v) {
    #pragma unroll
    for (int o = 16; o > 0; o >>= 1) v = fmaxf(v, __shfl_xor_sync(0xffffffff, v, o));
    return v;
}

// ---------------- kernel 1: disease CE + row means + small per-token losses --
__global__ void __launch_bounds__(128) disease_ce_kernel(
        const float* __restrict__ logits, const int* __restrict__ targets,
        const float* __restrict__ tte, const float* __restrict__ ttgt,
        const float* __restrict__ risk, const int* __restrict__ rtgt,
        const float* __restrict__ unc,
        const float* __restrict__ curves, const float* __restrict__ ttimes,
        int n_surv, int T) {
    int row  = blockIdx.x;
    int t    = threadIdx.x;
    int slot = row & (NSLOT - 1);
    const float4* base = reinterpret_cast<const float4*>(logits) + (size_t)row * NVEC;

    float4 v0 = base[t];                  // t in [0,128) < 350
    float4 v1 = base[t + 128];            // < 350
    bool   h2 = (t + 256) < NVEC;         // t < 94
    float4 v2 = h2 ? base[t + 256]
                   : make_float4(-INFINITY, -INFINITY, -INFINITY, -INFINITY);

    // ---- fused survival row mean: warp 1 handles row < n_surv ----
    if (row < n_surv && t >= 32 && t < 64) {
        int lane = t - 32;
        const float* crow = curves + (size_t)row * T;
        float s = 0.f;
        for (int k = lane; k < T; k += 32) s += crow[k];
        #pragma unroll
        for (int o = 16; o > 0; o >>= 1) s += __shfl_xor_sync(0xffffffff, s, o, 32);
        if (lane == 0) g_tm[row] = make_float2(ttimes[row], s / (float)T);
    }

    // ---- fused per-token scalar losses (idle-lane work) ----
    if (t == 96) {
        float x    = tte[row];
        float rate = 1.0f / (x + EPSF);
        float tl   = __logf(rate + EPSF) - rate * ttgt[row];
        slot_add(M_TIME, slot, tl);
        slot_add(M_UNC,  slot, unc[row]);
    } else if (t == 64) {
        int r = rtgt[row];
        if (r >= 0) {
            const float* rl = risk + (size_t)row * 5;
            float a0 = rl[0], a1 = rl[1], a2 = rl[2], a3 = rl[3], a4 = rl[4];
            float mm = fmaxf(fmaxf(fmaxf(a0, a1), fmaxf(a2, a3)), a4);
            float ss = __expf(a0 - mm) + __expf(a1 - mm) + __expf(a2 - mm)
                     + __expf(a3 - mm) + __expf(a4 - mm);
            float xt = (r == 0) ? a0 : (r == 1) ? a1 : (r == 2) ? a2 : (r == 3) ? a3 : a4;
            slot_add(M_RISK, slot, -(xt - mm - __logf(ss)));
            slot_add(M_RCNT, slot, 1.0f);
        }
    }

    float m = fmaxf(fmaxf(fmaxf(v0.x, v0.y), fmaxf(v0.z, v0.w)),
                    fmaxf(fmaxf(v1.x, v1.y), fmaxf(v1.z, v1.w)));
    m = fmaxf(m, fmaxf(fmaxf(v2.x, v2.y), fmaxf(v2.z, v2.w)));

    __shared__ float sred[4];
    __shared__ float s_tval;

    int tgt = targets[row];
    if (tgt >= 0) {
        int vi = tgt >> 2;
        if ((vi & 127) == t) {
            float4 v = (vi < 128) ? v0 : ((vi < 256) ? v1 : v2);
            int l = tgt & 3;
            s_tval = (l == 0) ? v.x : (l == 1) ? v.y : (l == 2) ? v.z : v.w;
        }
    }

    m = warp_max(m);
    int warp = t >> 5;
    if ((t & 31) == 0) sred[warp] = m;
    __syncthreads();
    m = fmaxf(fmaxf(sred[0], sred[1]), fmaxf(sred[2], sred[3]));

    float s = __expf(v0.x - m) + __expf(v0.y - m) + __expf(v0.z - m) + __expf(v0.w - m)
            + __expf(v1.x - m) + __expf(v1.y - m) + __expf(v1.z - m) + __expf(v1.w - m);
    if (h2)
        s += __expf(v2.x - m) + __expf(v2.y - m) + __expf(v2.z - m) + __expf(v2.w - m);

    s = warp_sum(s);
    __syncthreads();
    if ((t & 31) == 0) sred[warp] = s;
    __syncthreads();

    if (t == 0 && tgt >= 0) {
        float S   = sred[0] + sred[1] + sred[2] + sred[3];
        float nll = -(s_tval - m - __logf(S));
        slot_add(M_DIS,  slot, nll);
        slot_add(M_DCNT, slot, 1.0f);
    }
}

// ------- kernel 2: concordance — balanced triangle, j-split, MLP-4 ----------
// process i-group [i0, i0+IGRP); this block handles j-half `h` of the sweep
__device__ __forceinline__ void conc_group(
        int i0, int n, const int* __restrict__ events,
        int tid, int lane, int wrp, int h,
        unsigned& cnt, unsigned& conc2) {
    float ti[IGRP], mi[IGRP];
    bool  ev[IGRP];
    bool  any = false;
    #pragma unroll
    for (int k = 0; k < IGRP; k++) {
        float2 v = __ldg(&g_tm[i0 + k]);   // L2 broadcast
        ti[k] = v.x; mi[k] = v.y;
        ev[k] = (i0 + k < n) && (__ldg(&events[i0 + k]) == 1);
        any |= ev[k];
    }
    if (!any) return;

    // peel j in (i0, i0+IGRP): thread 0 of the h==0 half only
    if (tid == 0 && h == 0) {
        for (int j = i0 + 1; j < i0 + IGRP && j < n; j++) {
            float2 jm = __ldg(&g_tm[j]);
            for (int k = 0; k < j - i0; k++) {
                if (ev[k] && ti[k] < jm.x) {
                    cnt++;
                    conc2 += (mi[k] < jm.y) ? 2u : ((mi[k] == jm.y) ? 1u : 0u);
                }
            }
        }
    }

    // main sweep: 2 blocks x 4 warps = 8-way sweep, 4-tile unroll (MLP=4)
    int jstart = i0 + IGRP;
    int sweep  = wrp + 4 * h;              // 0..7
    for (int jb = jstart + sweep * 128; jb < n; jb += 1024) {
        float tj[4], mj[4];
        #pragma unroll
        for (int u = 0; u < 4; u++) {
            int j = jb + u * 32 + lane;
            if (j < n) {
                float2 v = __ldg(&g_tm[j]);
                tj[u] = v.x; mj[u] = v.y;
            } else {
                tj[u] = -INFINITY; mj[u] = 0.f;   // ti < -inf never true
            }
        }
        #pragma unroll
        for (int u = 0; u < 4; u++) {
            #pragma unroll
            for (int k = 0; k < IGRP; k++) {
                if (!ev[k]) continue;              // warp-uniform branch
                bool c1 = (ti[k] < tj[u]);
                cnt   += c1;
                conc2 += (unsigned)(c1 & (mi[k] <  mj[u]))
                       + (unsigned)(c1 & (mi[k] <= mj[u]));
            }
        }
    }
}

__global__ void __launch_bounds__(128) concordance_kernel(
        const int* __restrict__ events, int n, int ngrp,
        float* __restrict__ out, int n_tok) {
    int tid  = threadIdx.x;
    int lane = tid & 31;
    int wrp  = tid >> 5;                   // 0..3

    unsigned cnt = 0, conc2 = 0;           // per-lane; conc scaled by 2

    // block = (group-pair p, j-half h); pair p owns groups p and ngrp-1-p
    int p  = blockIdx.x >> 1;
    int h  = blockIdx.x & 1;
    int g1 = p;
    int g2 = ngrp - 1 - p;
    conc_group(g1 * IGRP, n, events, tid, lane, wrp, h, cnt, conc2);
    if (g2 != g1)
        conc_group(g2 * IGRP, n, events, tid, lane, wrp, h, cnt, conc2);

    cnt   = warp_sum_u(cnt);
    conc2 = warp_sum_u(conc2);
    __shared__ unsigned sc_[4], si_[4];
    if (lane == 0) { sc_[wrp] = conc2; si_[wrp] = cnt; }
    __syncthreads();
    if (tid == 0) {
        unsigned C2 = sc_[0] + sc_[1] + sc_[2] + sc_[3];
        unsigned P  = si_[0] + si_[1] + si_[2] + si_[3];
        if (P > 0) {
            int slot = blockIdx.x & (NSLOT - 1);
            slot_add(M_CONC, slot, 0.5f * (float)C2);
            slot_add(M_PAIR, slot, (float)P);
        }
    }

    // ---- last-done block finalizes and resets ----
    __shared__ bool amLast;
    if (tid == 0) {
        __threadfence();
        unsigned v = atomicAdd(&g_done, 1u);
        amLast = (v == gridDim.x - 1);
    }
    __syncthreads();
    if (!amLast) return;

    __shared__ float tot[NMET];
    if (tid < NMET) {
        float s = 0.f;
        #pragma unroll
        for (int k = 0; k < NSLOT; k++) s += g_acc[tid][k * SSTRIDE];
        tot[tid] = s;
    }
    __syncthreads();
    if (tid == 0) {
        float dcnt    = tot[M_DCNT] > 0.f ? tot[M_DCNT] : 1.f;
        float rcnt    = tot[M_RCNT] > 0.f ? tot[M_RCNT] : 1.f;
        float disease = tot[M_DIS] / dcnt;
        float timel   = -tot[M_TIME] / (float)n_tok;
        float riskl   = tot[M_RISK] / rcnt;
        float surv    = (tot[M_PAIR] > 0.f) ? 1.0f - tot[M_CONC] / tot[M_PAIR] : 0.0f;
        float u       = (tot[M_UNC] / (float)n_tok) * 0.01f;
        out[0] = disease;
        out[1] = timel;
        out[2] = riskl;
        out[3] = surv;
        out[4] = u;
        out[5] = disease + timel + riskl + surv + u;
        g_done = 0u;
    }
    // reset accumulators for the next execution (128 threads, 256 entries)
    for (int e = tid; e < NMET * NSLOT; e += 128)
        g_acc[e / NSLOT][(e % NSLOT) * SSTRIDE] = 0.f;
}

// ---------------- launch ----------------
extern "C" void kernel_launch(void* const* d_in, const int* in_sizes, int n_in,
                              void* d_out, int out_size) {
    const float* disease_logits = (const float*)d_in[0];
    const int*   disease_tgt    = (const int*)d_in[1];
    const float* tte            = (const float*)d_in[2];
    const float* ttgt           = (const float*)d_in[3];
    const float* risk           = (const float*)d_in[4];
    const int*   risk_tgt       = (const int*)d_in[5];
    const float* curves         = (const float*)d_in[6];
    const float* surv_tgt       = (const float*)d_in[7];
    const int*   events         = (const int*)d_in[8];
    const float* unc            = (const float*)d_in[9];
    float*       out            = (float*)d_out;

    int n_tok = in_sizes[1];            // 16384
    int n     = in_sizes[7];            // 4096
    int T     = in_sizes[6] / n;        // 120

    disease_ce_kernel<<<n_tok, 128>>>(disease_logits, disease_tgt,
                                      tte, ttgt, risk, risk_tgt, unc,
                                      curves, surv_tgt, n, T);
    int ngrp        = (n + IGRP - 1) / IGRP;       // 1024
    int conc_blocks = ((ngrp + 1) / 2) * 2;        // 1024: 512 pairs x 2 j-halves
    concordance_kernel<<<conc_blocks, 128>>>(events, n, ngrp, out, n_tok);
}